// round 6
// baseline (speedup 1.0000x reference)
#include <cuda_runtime.h>
#include <cstddef>

#define BB 8
#define CC 256
#define FF 16384
#define TF 64
#define KC 32
#define NCHUNK 32
#define NSTEPS 20

// ---- scratch (no allocations allowed: device globals) ----
__device__ float g_init[BB*FF];
__device__ float g_pred[BB*FF];
__device__ float g_scores[BB*FF];
__device__ unsigned char g_done[BB*FF];
__device__ unsigned char g_bnd[BB*FF];
__device__ unsigned char g_reach[BB*FF];

// ---- packed f32x2 helpers (FFMA2: 2x FFMA throughput, PTX-only path) ----
__device__ __forceinline__ unsigned long long pack2(float x, float y) {
    unsigned long long r;
    asm("mov.b64 %0, {%1, %2};" : "=l"(r) : "f"(x), "f"(y));
    return r;
}
__device__ __forceinline__ void unpack2(unsigned long long p, float& x, float& y) {
    asm("mov.b64 {%0, %1}, %2;" : "=f"(x), "=f"(y) : "l"(p));
}
__device__ __forceinline__ void ffma2(unsigned long long& d, unsigned long long a, unsigned long long b) {
    asm("fma.rn.f32x2 %0, %1, %2, %0;" : "+l"(d) : "l"(a), "l"(b));
}
__device__ __forceinline__ float sigm(float z) { return 1.0f / (1.0f + expf(-z)); }

// ---- GEMM inner chunk: 32 k-steps, per-thread 4 faces x 16 out-channels ----
template<bool WI>
__device__ __forceinline__ void compute_chunk(
    unsigned long long acc[4][4][2], float isc[4],
    const float (*As)[TF], const float (*Bs)[CC],
    const float* Wm_s, int c0, int tx, int ty)
{
#pragma unroll 8
    for (int kk = 0; kk < KC; ++kk) {
        float4 av = *(const float4*)&As[kk][ty*4];       // 4 faces, broadcast over tx
        if (WI) {
            float w = Wm_s[c0 + kk];                     // init_scores dot (self source only)
            isc[0] += av.x*w; isc[1] += av.y*w; isc[2] += av.z*w; isc[3] += av.w*w;
        }
        unsigned long long aa[4];
        aa[0] = pack2(av.x, av.x); aa[1] = pack2(av.y, av.y);
        aa[2] = pack2(av.z, av.z); aa[3] = pack2(av.w, av.w);
#pragma unroll
        for (int q = 0; q < 4; ++q) {
            ulonglong2 bv = *(const ulonglong2*)&Bs[kk][q*64 + tx*4]; // 4 consecutive oc
#pragma unroll
            for (int i = 0; i < 4; ++i) {
                ffma2(acc[i][q][0], aa[i], bv.x);
                ffma2(acc[i][q][1], aa[i], bv.y);
            }
        }
    }
}

// ============================================================================
// K1: gather-GEMM + bias + instance-norm + pred/init sigmoid heads
// grid (FF/TF, BB), 256 threads. Writes normalized h into d_out features.
// ============================================================================
__global__ void __launch_bounds__(256)
conv_kernel(const float* __restrict__ x, const int* __restrict__ adj,
            const float* __restrict__ Wc, const float* __restrict__ bc,
            const float* __restrict__ Wm, const float* __restrict__ bm,
            float* __restrict__ out)
{
    __shared__ __align__(16) float As[KC][TF];    // A tile, [k][face] for LDS.128 over faces
    __shared__ __align__(16) float Bs[KC][CC];    // W_conv tile
    __shared__ int   Ssrc[4][TF];                 // gather sources per face (self + 3 nbrs)
    __shared__ float Wm_s[CC];
    __shared__ float bc_s[CC];

    const int t  = threadIdx.x;
    const int b  = blockIdx.y;
    const int f0 = blockIdx.x * TF;
    const int tx = t & 15;       // out-channel group
    const int ty = t >> 4;       // face group (4 faces each)

    Wm_s[t] = Wm[t];
    bc_s[t] = bc[t];
    if (t < TF) Ssrc[0][t] = f0 + t;
    if (t < 3*TF) {
        int s  = t / TF + 1;
        int tf = t % TF;
        Ssrc[s][tf] = adj[((size_t)b*FF + (size_t)(f0 + tf))*3 + (s - 1)];
    }
    const float bm0 = bm[0];
    __syncthreads();

    unsigned long long acc[4][4][2];
#pragma unroll
    for (int i = 0; i < 4; ++i)
#pragma unroll
        for (int q = 0; q < 4; ++q) { acc[i][q][0] = 0ull; acc[i][q][1] = 0ull; }
    float isc[4] = {0.f, 0.f, 0.f, 0.f};

    const float* xb = x + (size_t)b * CC * FF;

    for (int kc = 0; kc < NCHUNK; ++kc) {
        const int s  = kc >> 3;           // source index (chunks stay within one source)
        const int c0 = (kc & 7) << 5;     // channel base within source
        float  a_r[8];
        float4 b_r[8];
        const int* srow = Ssrc[s];
        // prefetch into registers while previous chunk still computes on smem
#pragma unroll
        for (int r = 0; r < 8; ++r) {
            int e = t + 256*r;
            int kk = e >> 6, tf = e & 63;
            a_r[r] = __ldg(xb + (size_t)(c0 + kk)*FF + srow[tf]);
        }
#pragma unroll
        for (int r = 0; r < 8; ++r) {
            int e = t + 256*r;
            int kk = e >> 6, oc4 = e & 63;
            b_r[r] = __ldg((const float4*)(Wc + (size_t)(s*CC + c0 + kk)*CC) + oc4);
        }
        __syncthreads();                 // previous compute done -> safe to overwrite
#pragma unroll
        for (int r = 0; r < 8; ++r) {
            int e = t + 256*r;
            As[e >> 6][e & 63] = a_r[r];
        }
#pragma unroll
        for (int r = 0; r < 8; ++r) {
            int e = t + 256*r;
            *(float4*)&Bs[e >> 6][(e & 63)*4] = b_r[r];
        }
        __syncthreads();
        if (s == 0) compute_chunk<true >(acc, isc, As, Bs, Wm_s, c0, tx, ty);
        else        compute_chunk<false>(acc, isc, As, Bs, Wm_s, c0, tx, ty);
    }

    // ---- epilogue: bias, instance norm over 256 channels, heads, store ----
    float hv[4][16];
#pragma unroll
    for (int i = 0; i < 4; ++i) {
#pragma unroll
        for (int q = 0; q < 4; ++q) {
            float x0, x1, x2, x3;
            unpack2(acc[i][q][0], x0, x1);
            unpack2(acc[i][q][1], x2, x3);
            int ocb = q*64 + tx*4;
            hv[i][q*4+0] = x0 + bc_s[ocb+0];
            hv[i][q*4+1] = x1 + bc_s[ocb+1];
            hv[i][q*4+2] = x2 + bc_s[ocb+2];
            hv[i][q*4+3] = x3 + bc_s[ocb+3];
        }
    }
#pragma unroll
    for (int i = 0; i < 4; ++i) {
        float s1 = 0.f, s2 = 0.f;
#pragma unroll
        for (int j = 0; j < 16; ++j) { float v = hv[i][j]; s1 += v; s2 += v*v; }
#pragma unroll
        for (int off = 8; off >= 1; off >>= 1) {     // 16 tx-threads share a half-warp
            s1 += __shfl_xor_sync(0xffffffffu, s1, off);
            s2 += __shfl_xor_sync(0xffffffffu, s2, off);
        }
        const float mean = s1 * (1.f/256.f);
        const float var  = s2 * (1.f/256.f) - mean*mean;   // biased, matches jnp.var
        const float rstd = rsqrtf(var + 1e-5f);

        float pp = 0.f;
#pragma unroll
        for (int q = 0; q < 4; ++q) {
            int ocb = q*64 + tx*4;
#pragma unroll
            for (int v = 0; v < 4; ++v) {
                float hn = (hv[i][q*4+v] - mean) * rstd;
                hv[i][q*4+v] = hn;
                pp += hn * Wm_s[ocb+v];
            }
        }
#pragma unroll
        for (int off = 8; off >= 1; off >>= 1)
            pp += __shfl_xor_sync(0xffffffffu, pp, off);

        const int f = f0 + ty*4 + i;
        float* orow = out + ((size_t)(b*FF + f) << 8);
#pragma unroll
        for (int q = 0; q < 4; ++q) {
            float4 v4 = make_float4(hv[i][q*4+0], hv[i][q*4+1], hv[i][q*4+2], hv[i][q*4+3]);
            *(float4*)(orow + q*64 + tx*4) = v4;
        }
        if (tx == 0) {
            const int gf = b*FF + f;
            g_pred[gf] = sigm(pp + bm0);
            g_init[gf] = sigm(isc[i] + bm0);
        }
    }
}

// ============================================================================
// K2: 20-step flood fill. One block per batch; __syncthreads is the step
// barrier; state lives in device globals (L2-resident). Mirrors the scan body:
//   new = min(max(pred, scores), nbmax) at boundary; done |= boundary;
//   boundary' = scatter(adj, boundary) & ~done'
// Race-free: writers = boundary nodes, readers only read done neighbors,
// boundary ∩ done = ∅ (the step-0 anchor is the lone frontier member).
// ============================================================================
__global__ void __launch_bounds__(1024)
bfs_kernel(const int* __restrict__ adj, const int* __restrict__ anchors,
           float* __restrict__ out_sc, int write_scores)
{
    const int b = blockIdx.x;
    const int t = threadIdx.x;
    float* sc                = g_scores + b*FF;
    const float* pr          = g_pred   + b*FF;
    unsigned char* dn        = g_done   + b*FF;
    unsigned char* bd        = g_bnd    + b*FF;
    unsigned char* rc        = g_reach  + b*FF;
    const int* am            = adj + (size_t)b*FF*3;

    for (int f = t; f < FF; f += 1024) {
        sc[f] = g_init[b*FF + f];
        dn[f] = 0; bd[f] = 0; rc[f] = 0;
    }
    __syncthreads();
    if (t == 0) { int a = anchors[b]; dn[a] = 1; bd[a] = 1; }
    __syncthreads();

    for (int step = 0; step < NSTEPS; ++step) {
        // phase A+C: score update + frontier scatter (disjoint arrays)
        for (int f = t; f < FF; f += 1024) {
            if (bd[f]) {
                int j0 = am[3*f], j1 = am[3*f+1], j2 = am[3*f+2];
                float m = -1.f; bool any = false;
                if (dn[j0]) { any = true; m = fmaxf(m, sc[j0]); }
                if (dn[j1]) { any = true; m = fmaxf(m, sc[j1]); }
                if (dn[j2]) { any = true; m = fmaxf(m, sc[j2]); }
                float nbmax = any ? m : 1.0f;
                sc[f] = fminf(fmaxf(pr[f], sc[f]), nbmax);
                rc[j0] = 1; rc[j1] = 1; rc[j2] = 1;
            }
        }
        __syncthreads();
        // phase D: advance done / boundary, clear reach
        for (int f = t; f < FF; f += 1024) {
            unsigned char d = dn[f] | bd[f];
            bd[f] = (rc[f] && !d) ? 1 : 0;
            dn[f] = d;
            rc[f] = 0;
        }
        __syncthreads();
    }
    if (write_scores)
        for (int f = t; f < FF; f += 1024)
            out_sc[b*FF + f] = sc[f];
}

// ============================================================================
// K3: faces never visited keep their original features.
// ============================================================================
__global__ void blend_kernel(const float* __restrict__ x, float* __restrict__ out)
{
    int idx = blockIdx.x * blockDim.x + threadIdx.x;
    if (idx >= BB*FF) return;
    if (!g_done[idx]) {
        int b = idx >> 14;
        int f = idx & (FF - 1);
        const float* xb = x + (size_t)b*CC*FF + f;
        float* o = out + (size_t)idx * CC;
#pragma unroll 8
        for (int c = 0; c < CC; ++c) o[c] = xb[(size_t)c * FF];
    }
}

extern "C" void kernel_launch(void* const* d_in, const int* in_sizes, int n_in,
                              void* d_out, int out_size)
{
    const float* x       = (const float*)d_in[0];   // [B, C, F]
    const int*   adj     = (const int*)  d_in[1];   // [B, F, 3]
    const int*   anchors = (const int*)  d_in[2];   // [B]
    const float* Wc      = (const float*)d_in[3];   // [4C, C]
    const float* bc      = (const float*)d_in[4];   // [C]
    const float* Wm      = (const float*)d_in[5];   // [C, 1]
    const float* bm      = (const float*)d_in[6];   // [1]
    float* out = (float*)d_out;

    const long long FEAT = (long long)BB * FF * CC;           // features first
    const int ws = (out_size >= FEAT + (long long)BB*FF) ? 1 : 0;  // then scores

    conv_kernel<<<dim3(FF/TF, BB), 256>>>(x, adj, Wc, bc, Wm, bm, out);
    bfs_kernel<<<BB, 1024>>>(adj, anchors, out + FEAT, ws);
    blend_kernel<<<(BB*FF + 255)/256, 256>>>(x, out);
}

// round 7
// speedup vs baseline: 1.0005x; 1.0005x over previous
#include <cuda_runtime.h>
#include <cstddef>

#define BB 8
#define CC 256
#define FF 16384
#define TF 64
#define KC 32
#define NCHUNK 32
#define NSTEPS 20

// ---- scratch (no allocations allowed: device globals) ----
__device__ float g_init[BB*FF];
__device__ float g_pred[BB*FF];
__device__ float g_scores[BB*FF];
__device__ unsigned char g_done[BB*FF];
__device__ unsigned char g_bnd[BB*FF];
__device__ unsigned char g_reach[BB*FF];

// ---- packed f32x2 helpers (FFMA2: 2x FFMA throughput, PTX-only path) ----
__device__ __forceinline__ unsigned long long pack2(float x, float y) {
    unsigned long long r;
    asm("mov.b64 %0, {%1, %2};" : "=l"(r) : "f"(x), "f"(y));
    return r;
}
__device__ __forceinline__ void unpack2(unsigned long long p, float& x, float& y) {
    asm("mov.b64 {%0, %1}, %2;" : "=f"(x), "=f"(y) : "l"(p));
}
__device__ __forceinline__ void ffma2(unsigned long long& d, unsigned long long a, unsigned long long b) {
    asm("fma.rn.f32x2 %0, %1, %2, %0;" : "+l"(d) : "l"(a), "l"(b));
}
__device__ __forceinline__ float sigm(float z) { return 1.0f / (1.0f + expf(-z)); }

// ---- GEMM inner chunk: 32 k-steps, per-thread 4 faces x 16 out-channels ----
template<bool WI>
__device__ __forceinline__ void compute_chunk(
    unsigned long long acc[4][4][2], float isc[4],
    const float (*As)[TF], const float (*Bs)[CC],
    const float* Wm_s, int c0, int tx, int ty)
{
#pragma unroll 8
    for (int kk = 0; kk < KC; ++kk) {
        float4 av = *(const float4*)&As[kk][ty*4];       // 4 faces, broadcast over tx
        if (WI) {
            float w = Wm_s[c0 + kk];                     // init_scores dot (self source only)
            isc[0] += av.x*w; isc[1] += av.y*w; isc[2] += av.z*w; isc[3] += av.w*w;
        }
        unsigned long long aa[4];
        aa[0] = pack2(av.x, av.x); aa[1] = pack2(av.y, av.y);
        aa[2] = pack2(av.z, av.z); aa[3] = pack2(av.w, av.w);
#pragma unroll
        for (int q = 0; q < 4; ++q) {
            ulonglong2 bv = *(const ulonglong2*)&Bs[kk][q*64 + tx*4]; // 4 consecutive oc
#pragma unroll
            for (int i = 0; i < 4; ++i) {
                ffma2(acc[i][q][0], aa[i], bv.x);
                ffma2(acc[i][q][1], aa[i], bv.y);
            }
        }
    }
}

// ============================================================================
// K1: gather-GEMM + bias + instance-norm + pred/init sigmoid heads
// grid (FF/TF, BB), 256 threads. Writes normalized h into d_out features.
// ============================================================================
__global__ void __launch_bounds__(256)
conv_kernel(const float* __restrict__ x, const int* __restrict__ adj,
            const float* __restrict__ Wc, const float* __restrict__ bc,
            const float* __restrict__ Wm, const float* __restrict__ bm,
            float* __restrict__ out)
{
    __shared__ __align__(16) float As[KC][TF];    // A tile, [k][face] for LDS.128 over faces
    __shared__ __align__(16) float Bs[KC][CC];    // W_conv tile
    __shared__ int   Ssrc[4][TF];                 // gather sources per face (self + 3 nbrs)
    __shared__ float Wm_s[CC];
    __shared__ float bc_s[CC];

    const int t  = threadIdx.x;
    const int b  = blockIdx.y;
    const int f0 = blockIdx.x * TF;
    const int tx = t & 15;       // out-channel group
    const int ty = t >> 4;       // face group (4 faces each)

    Wm_s[t] = Wm[t];
    bc_s[t] = bc[t];
    if (t < TF) Ssrc[0][t] = f0 + t;
    if (t < 3*TF) {
        int s  = t / TF + 1;
        int tf = t % TF;
        Ssrc[s][tf] = adj[((size_t)b*FF + (size_t)(f0 + tf))*3 + (s - 1)];
    }
    const float bm0 = bm[0];
    __syncthreads();

    unsigned long long acc[4][4][2];
#pragma unroll
    for (int i = 0; i < 4; ++i)
#pragma unroll
        for (int q = 0; q < 4; ++q) { acc[i][q][0] = 0ull; acc[i][q][1] = 0ull; }
    float isc[4] = {0.f, 0.f, 0.f, 0.f};

    const float* xb = x + (size_t)b * CC * FF;

    for (int kc = 0; kc < NCHUNK; ++kc) {
        const int s  = kc >> 3;           // source index (chunks stay within one source)
        const int c0 = (kc & 7) << 5;     // channel base within source
        float  a_r[8];
        float4 b_r[8];
        const int* srow = Ssrc[s];
        // prefetch into registers while previous chunk still computes on smem
#pragma unroll
        for (int r = 0; r < 8; ++r) {
            int e = t + 256*r;
            int kk = e >> 6, tf = e & 63;
            a_r[r] = __ldg(xb + (size_t)(c0 + kk)*FF + srow[tf]);
        }
#pragma unroll
        for (int r = 0; r < 8; ++r) {
            int e = t + 256*r;
            int kk = e >> 6, oc4 = e & 63;
            b_r[r] = __ldg((const float4*)(Wc + (size_t)(s*CC + c0 + kk)*CC) + oc4);
        }
        __syncthreads();                 // previous compute done -> safe to overwrite
#pragma unroll
        for (int r = 0; r < 8; ++r) {
            int e = t + 256*r;
            As[e >> 6][e & 63] = a_r[r];
        }
#pragma unroll
        for (int r = 0; r < 8; ++r) {
            int e = t + 256*r;
            *(float4*)&Bs[e >> 6][(e & 63)*4] = b_r[r];
        }
        __syncthreads();
        if (s == 0) compute_chunk<true >(acc, isc, As, Bs, Wm_s, c0, tx, ty);
        else        compute_chunk<false>(acc, isc, As, Bs, Wm_s, c0, tx, ty);
    }

    // ---- epilogue: bias, instance norm over 256 channels, heads, store ----
    float hv[4][16];
#pragma unroll
    for (int i = 0; i < 4; ++i) {
#pragma unroll
        for (int q = 0; q < 4; ++q) {
            float x0, x1, x2, x3;
            unpack2(acc[i][q][0], x0, x1);
            unpack2(acc[i][q][1], x2, x3);
            int ocb = q*64 + tx*4;
            hv[i][q*4+0] = x0 + bc_s[ocb+0];
            hv[i][q*4+1] = x1 + bc_s[ocb+1];
            hv[i][q*4+2] = x2 + bc_s[ocb+2];
            hv[i][q*4+3] = x3 + bc_s[ocb+3];
        }
    }
#pragma unroll
    for (int i = 0; i < 4; ++i) {
        float s1 = 0.f, s2 = 0.f;
#pragma unroll
        for (int j = 0; j < 16; ++j) { float v = hv[i][j]; s1 += v; s2 += v*v; }
#pragma unroll
        for (int off = 8; off >= 1; off >>= 1) {     // 16 tx-threads share a half-warp
            s1 += __shfl_xor_sync(0xffffffffu, s1, off);
            s2 += __shfl_xor_sync(0xffffffffu, s2, off);
        }
        const float mean = s1 * (1.f/256.f);
        const float var  = s2 * (1.f/256.f) - mean*mean;   // biased, matches jnp.var
        const float rstd = rsqrtf(var + 1e-5f);

        float pp = 0.f;
#pragma unroll
        for (int q = 0; q < 4; ++q) {
            int ocb = q*64 + tx*4;
#pragma unroll
            for (int v = 0; v < 4; ++v) {
                float hn = (hv[i][q*4+v] - mean) * rstd;
                hv[i][q*4+v] = hn;
                pp += hn * Wm_s[ocb+v];
            }
        }
#pragma unroll
        for (int off = 8; off >= 1; off >>= 1)
            pp += __shfl_xor_sync(0xffffffffu, pp, off);

        const int f = f0 + ty*4 + i;
        float* orow = out + ((size_t)(b*FF + f) << 8);
#pragma unroll
        for (int q = 0; q < 4; ++q) {
            float4 v4 = make_float4(hv[i][q*4+0], hv[i][q*4+1], hv[i][q*4+2], hv[i][q*4+3]);
            *(float4*)(orow + q*64 + tx*4) = v4;
        }
        if (tx == 0) {
            const int gf = b*FF + f;
            g_pred[gf] = sigm(pp + bm0);
            g_init[gf] = sigm(isc[i] + bm0);
        }
    }
}

// ============================================================================
// K2: 20-step flood fill. One block per batch; __syncthreads is the step
// barrier; state lives in device globals (L2-resident). Mirrors the scan body:
//   new = min(max(pred, scores), nbmax) at boundary; done |= boundary;
//   boundary' = scatter(adj, boundary) & ~done'
// Race-free: writers = boundary nodes, readers only read done neighbors,
// boundary ∩ done = ∅ (the step-0 anchor is the lone frontier member).
// ============================================================================
__global__ void __launch_bounds__(1024)
bfs_kernel(const int* __restrict__ adj, const int* __restrict__ anchors,
           float* __restrict__ out_sc, int write_scores)
{
    const int b = blockIdx.x;
    const int t = threadIdx.x;
    float* sc                = g_scores + b*FF;
    const float* pr          = g_pred   + b*FF;
    unsigned char* dn        = g_done   + b*FF;
    unsigned char* bd        = g_bnd    + b*FF;
    unsigned char* rc        = g_reach  + b*FF;
    const int* am            = adj + (size_t)b*FF*3;

    for (int f = t; f < FF; f += 1024) {
        sc[f] = g_init[b*FF + f];
        dn[f] = 0; bd[f] = 0; rc[f] = 0;
    }
    __syncthreads();
    if (t == 0) { int a = anchors[b]; dn[a] = 1; bd[a] = 1; }
    __syncthreads();

    for (int step = 0; step < NSTEPS; ++step) {
        // phase A+C: score update + frontier scatter (disjoint arrays)
        for (int f = t; f < FF; f += 1024) {
            if (bd[f]) {
                int j0 = am[3*f], j1 = am[3*f+1], j2 = am[3*f+2];
                float m = -1.f; bool any = false;
                if (dn[j0]) { any = true; m = fmaxf(m, sc[j0]); }
                if (dn[j1]) { any = true; m = fmaxf(m, sc[j1]); }
                if (dn[j2]) { any = true; m = fmaxf(m, sc[j2]); }
                float nbmax = any ? m : 1.0f;
                sc[f] = fminf(fmaxf(pr[f], sc[f]), nbmax);
                rc[j0] = 1; rc[j1] = 1; rc[j2] = 1;
            }
        }
        __syncthreads();
        // phase D: advance done / boundary, clear reach
        for (int f = t; f < FF; f += 1024) {
            unsigned char d = dn[f] | bd[f];
            bd[f] = (rc[f] && !d) ? 1 : 0;
            dn[f] = d;
            rc[f] = 0;
        }
        __syncthreads();
    }
    if (write_scores)
        for (int f = t; f < FF; f += 1024)
            out_sc[b*FF + f] = sc[f];
}

// ============================================================================
// K3: faces never visited keep their original features.
// ============================================================================
__global__ void blend_kernel(const float* __restrict__ x, float* __restrict__ out)
{
    int idx = blockIdx.x * blockDim.x + threadIdx.x;
    if (idx >= BB*FF) return;
    if (!g_done[idx]) {
        int b = idx >> 14;
        int f = idx & (FF - 1);
        const float* xb = x + (size_t)b*CC*FF + f;
        float* o = out + (size_t)idx * CC;
#pragma unroll 8
        for (int c = 0; c < CC; ++c) o[c] = xb[(size_t)c * FF];
    }
}

extern "C" void kernel_launch(void* const* d_in, const int* in_sizes, int n_in,
                              void* d_out, int out_size)
{
    const float* x       = (const float*)d_in[0];   // [B, C, F]
    const int*   adj     = (const int*)  d_in[1];   // [B, F, 3]
    const int*   anchors = (const int*)  d_in[2];   // [B]
    const float* Wc      = (const float*)d_in[3];   // [4C, C]
    const float* bc      = (const float*)d_in[4];   // [C]
    const float* Wm      = (const float*)d_in[5];   // [C, 1]
    const float* bm      = (const float*)d_in[6];   // [1]
    float* out = (float*)d_out;

    const long long FEAT = (long long)BB * FF * CC;           // features first
    const int ws = (out_size >= FEAT + (long long)BB*FF) ? 1 : 0;  // then scores

    conv_kernel<<<dim3(FF/TF, BB), 256>>>(x, adj, Wc, bc, Wm, bm, out);
    bfs_kernel<<<BB, 1024>>>(adj, anchors, out + FEAT, ws);
    blend_kernel<<<(BB*FF + 255)/256, 256>>>(x, out);
}

// round 8
// speedup vs baseline: 1.0012x; 1.0007x over previous
#include <cuda_runtime.h>
#include <cstddef>

#define BB 8
#define CC 256
#define FF 16384
#define TF 64
#define KC 32
#define NCHUNK 32
#define NSTEPS 20

// ---- scratch (no allocations allowed: device globals) ----
__device__ float g_init[BB*FF];
__device__ float g_pred[BB*FF];
__device__ float g_scores[BB*FF];
__device__ unsigned char g_done[BB*FF];
__device__ unsigned char g_bnd[BB*FF];
__device__ unsigned char g_reach[BB*FF];

// ---- packed f32x2 helpers (FFMA2: 2x FFMA throughput, PTX-only path) ----
__device__ __forceinline__ unsigned long long pack2(float x, float y) {
    unsigned long long r;
    asm("mov.b64 %0, {%1, %2};" : "=l"(r) : "f"(x), "f"(y));
    return r;
}
__device__ __forceinline__ void unpack2(unsigned long long p, float& x, float& y) {
    asm("mov.b64 {%0, %1}, %2;" : "=f"(x), "=f"(y) : "l"(p));
}
__device__ __forceinline__ void ffma2(unsigned long long& d, unsigned long long a, unsigned long long b) {
    asm("fma.rn.f32x2 %0, %1, %2, %0;" : "+l"(d) : "l"(a), "l"(b));
}
__device__ __forceinline__ float sigm(float z) { return 1.0f / (1.0f + expf(-z)); }

// ---- GEMM inner chunk: 32 k-steps, per-thread 4 faces x 16 out-channels ----
template<bool WI>
__device__ __forceinline__ void compute_chunk(
    unsigned long long acc[4][4][2], float isc[4],
    const float (*As)[TF], const float (*Bs)[CC],
    const float* Wm_s, int c0, int tx, int ty)
{
#pragma unroll 8
    for (int kk = 0; kk < KC; ++kk) {
        float4 av = *(const float4*)&As[kk][ty*4];       // 4 faces, broadcast over tx
        if (WI) {
            float w = Wm_s[c0 + kk];                     // init_scores dot (self source only)
            isc[0] += av.x*w; isc[1] += av.y*w; isc[2] += av.z*w; isc[3] += av.w*w;
        }
        unsigned long long aa[4];
        aa[0] = pack2(av.x, av.x); aa[1] = pack2(av.y, av.y);
        aa[2] = pack2(av.z, av.z); aa[3] = pack2(av.w, av.w);
#pragma unroll
        for (int q = 0; q < 4; ++q) {
            ulonglong2 bv = *(const ulonglong2*)&Bs[kk][q*64 + tx*4]; // 4 consecutive oc
#pragma unroll
            for (int i = 0; i < 4; ++i) {
                ffma2(acc[i][q][0], aa[i], bv.x);
                ffma2(acc[i][q][1], aa[i], bv.y);
            }
        }
    }
}

// ============================================================================
// K1: gather-GEMM + bias + instance-norm + pred/init sigmoid heads
// grid (FF/TF, BB), 256 threads. Writes normalized h into d_out features.
// ============================================================================
__global__ void __launch_bounds__(256)
conv_kernel(const float* __restrict__ x, const int* __restrict__ adj,
            const float* __restrict__ Wc, const float* __restrict__ bc,
            const float* __restrict__ Wm, const float* __restrict__ bm,
            float* __restrict__ out)
{
    __shared__ __align__(16) float As[KC][TF];    // A tile, [k][face] for LDS.128 over faces
    __shared__ __align__(16) float Bs[KC][CC];    // W_conv tile
    __shared__ int   Ssrc[4][TF];                 // gather sources per face (self + 3 nbrs)
    __shared__ float Wm_s[CC];
    __shared__ float bc_s[CC];

    const int t  = threadIdx.x;
    const int b  = blockIdx.y;
    const int f0 = blockIdx.x * TF;
    const int tx = t & 15;       // out-channel group
    const int ty = t >> 4;       // face group (4 faces each)

    Wm_s[t] = Wm[t];
    bc_s[t] = bc[t];
    if (t < TF) Ssrc[0][t] = f0 + t;
    if (t < 3*TF) {
        int s  = t / TF + 1;
        int tf = t % TF;
        Ssrc[s][tf] = adj[((size_t)b*FF + (size_t)(f0 + tf))*3 + (s - 1)];
    }
    const float bm0 = bm[0];
    __syncthreads();

    unsigned long long acc[4][4][2];
#pragma unroll
    for (int i = 0; i < 4; ++i)
#pragma unroll
        for (int q = 0; q < 4; ++q) { acc[i][q][0] = 0ull; acc[i][q][1] = 0ull; }
    float isc[4] = {0.f, 0.f, 0.f, 0.f};

    const float* xb = x + (size_t)b * CC * FF;

    for (int kc = 0; kc < NCHUNK; ++kc) {
        const int s  = kc >> 3;           // source index (chunks stay within one source)
        const int c0 = (kc & 7) << 5;     // channel base within source
        float  a_r[8];
        float4 b_r[8];
        const int* srow = Ssrc[s];
        // prefetch into registers while previous chunk still computes on smem
#pragma unroll
        for (int r = 0; r < 8; ++r) {
            int e = t + 256*r;
            int kk = e >> 6, tf = e & 63;
            a_r[r] = __ldg(xb + (size_t)(c0 + kk)*FF + srow[tf]);
        }
#pragma unroll
        for (int r = 0; r < 8; ++r) {
            int e = t + 256*r;
            int kk = e >> 6, oc4 = e & 63;
            b_r[r] = __ldg((const float4*)(Wc + (size_t)(s*CC + c0 + kk)*CC) + oc4);
        }
        __syncthreads();                 // previous compute done -> safe to overwrite
#pragma unroll
        for (int r = 0; r < 8; ++r) {
            int e = t + 256*r;
            As[e >> 6][e & 63] = a_r[r];
        }
#pragma unroll
        for (int r = 0; r < 8; ++r) {
            int e = t + 256*r;
            *(float4*)&Bs[e >> 6][(e & 63)*4] = b_r[r];
        }
        __syncthreads();
        if (s == 0) compute_chunk<true >(acc, isc, As, Bs, Wm_s, c0, tx, ty);
        else        compute_chunk<false>(acc, isc, As, Bs, Wm_s, c0, tx, ty);
    }

    // ---- epilogue: bias, instance norm over 256 channels, heads, store ----
    float hv[4][16];
#pragma unroll
    for (int i = 0; i < 4; ++i) {
#pragma unroll
        for (int q = 0; q < 4; ++q) {
            float x0, x1, x2, x3;
            unpack2(acc[i][q][0], x0, x1);
            unpack2(acc[i][q][1], x2, x3);
            int ocb = q*64 + tx*4;
            hv[i][q*4+0] = x0 + bc_s[ocb+0];
            hv[i][q*4+1] = x1 + bc_s[ocb+1];
            hv[i][q*4+2] = x2 + bc_s[ocb+2];
            hv[i][q*4+3] = x3 + bc_s[ocb+3];
        }
    }
#pragma unroll
    for (int i = 0; i < 4; ++i) {
        float s1 = 0.f, s2 = 0.f;
#pragma unroll
        for (int j = 0; j < 16; ++j) { float v = hv[i][j]; s1 += v; s2 += v*v; }
#pragma unroll
        for (int off = 8; off >= 1; off >>= 1) {     // 16 tx-threads share a half-warp
            s1 += __shfl_xor_sync(0xffffffffu, s1, off);
            s2 += __shfl_xor_sync(0xffffffffu, s2, off);
        }
        const float mean = s1 * (1.f/256.f);
        const float var  = s2 * (1.f/256.f) - mean*mean;   // biased, matches jnp.var
        const float rstd = rsqrtf(var + 1e-5f);

        float pp = 0.f;
#pragma unroll
        for (int q = 0; q < 4; ++q) {
            int ocb = q*64 + tx*4;
#pragma unroll
            for (int v = 0; v < 4; ++v) {
                float hn = (hv[i][q*4+v] - mean) * rstd;
                hv[i][q*4+v] = hn;
                pp += hn * Wm_s[ocb+v];
            }
        }
#pragma unroll
        for (int off = 8; off >= 1; off >>= 1)
            pp += __shfl_xor_sync(0xffffffffu, pp, off);

        const int f = f0 + ty*4 + i;
        float* orow = out + ((size_t)(b*FF + f) << 8);
#pragma unroll
        for (int q = 0; q < 4; ++q) {
            float4 v4 = make_float4(hv[i][q*4+0], hv[i][q*4+1], hv[i][q*4+2], hv[i][q*4+3]);
            *(float4*)(orow + q*64 + tx*4) = v4;
        }
        if (tx == 0) {
            const int gf = b*FF + f;
            g_pred[gf] = sigm(pp + bm0);
            g_init[gf] = sigm(isc[i] + bm0);
        }
    }
}

// ============================================================================
// K2: 20-step flood fill. One block per batch; __syncthreads is the step
// barrier; state lives in device globals (L2-resident). Mirrors the scan body:
//   new = min(max(pred, scores), nbmax) at boundary; done |= boundary;
//   boundary' = scatter(adj, boundary) & ~done'
// Race-free: writers = boundary nodes, readers only read done neighbors,
// boundary ∩ done = ∅ (the step-0 anchor is the lone frontier member).
// ============================================================================
__global__ void __launch_bounds__(1024)
bfs_kernel(const int* __restrict__ adj, const int* __restrict__ anchors,
           float* __restrict__ out_sc, int write_scores)
{
    const int b = blockIdx.x;
    const int t = threadIdx.x;
    float* sc                = g_scores + b*FF;
    const float* pr          = g_pred   + b*FF;
    unsigned char* dn        = g_done   + b*FF;
    unsigned char* bd        = g_bnd    + b*FF;
    unsigned char* rc        = g_reach  + b*FF;
    const int* am            = adj + (size_t)b*FF*3;

    for (int f = t; f < FF; f += 1024) {
        sc[f] = g_init[b*FF + f];
        dn[f] = 0; bd[f] = 0; rc[f] = 0;
    }
    __syncthreads();
    if (t == 0) { int a = anchors[b]; dn[a] = 1; bd[a] = 1; }
    __syncthreads();

    for (int step = 0; step < NSTEPS; ++step) {
        // phase A+C: score update + frontier scatter (disjoint arrays)
        for (int f = t; f < FF; f += 1024) {
            if (bd[f]) {
                int j0 = am[3*f], j1 = am[3*f+1], j2 = am[3*f+2];
                float m = -1.f; bool any = false;
                if (dn[j0]) { any = true; m = fmaxf(m, sc[j0]); }
                if (dn[j1]) { any = true; m = fmaxf(m, sc[j1]); }
                if (dn[j2]) { any = true; m = fmaxf(m, sc[j2]); }
                float nbmax = any ? m : 1.0f;
                sc[f] = fminf(fmaxf(pr[f], sc[f]), nbmax);
                rc[j0] = 1; rc[j1] = 1; rc[j2] = 1;
            }
        }
        __syncthreads();
        // phase D: advance done / boundary, clear reach
        for (int f = t; f < FF; f += 1024) {
            unsigned char d = dn[f] | bd[f];
            bd[f] = (rc[f] && !d) ? 1 : 0;
            dn[f] = d;
            rc[f] = 0;
        }
        __syncthreads();
    }
    if (write_scores)
        for (int f = t; f < FF; f += 1024)
            out_sc[b*FF + f] = sc[f];
}

// ============================================================================
// K3: faces never visited keep their original features.
// ============================================================================
__global__ void blend_kernel(const float* __restrict__ x, float* __restrict__ out)
{
    int idx = blockIdx.x * blockDim.x + threadIdx.x;
    if (idx >= BB*FF) return;
    if (!g_done[idx]) {
        int b = idx >> 14;
        int f = idx & (FF - 1);
        const float* xb = x + (size_t)b*CC*FF + f;
        float* o = out + (size_t)idx * CC;
#pragma unroll 8
        for (int c = 0; c < CC; ++c) o[c] = xb[(size_t)c * FF];
    }
}

extern "C" void kernel_launch(void* const* d_in, const int* in_sizes, int n_in,
                              void* d_out, int out_size)
{
    const float* x       = (const float*)d_in[0];   // [B, C, F]
    const int*   adj     = (const int*)  d_in[1];   // [B, F, 3]
    const int*   anchors = (const int*)  d_in[2];   // [B]
    const float* Wc      = (const float*)d_in[3];   // [4C, C]
    const float* bc      = (const float*)d_in[4];   // [C]
    const float* Wm      = (const float*)d_in[5];   // [C, 1]
    const float* bm      = (const float*)d_in[6];   // [1]
    float* out = (float*)d_out;

    const long long FEAT = (long long)BB * FF * CC;           // features first
    const int ws = (out_size >= FEAT + (long long)BB*FF) ? 1 : 0;  // then scores

    conv_kernel<<<dim3(FF/TF, BB), 256>>>(x, adj, Wc, bc, Wm, bm, out);
    bfs_kernel<<<BB, 1024>>>(adj, anchors, out + FEAT, ws);
    blend_kernel<<<(BB*FF + 255)/256, 256>>>(x, out);
}